// round 11
// baseline (speedup 1.0000x reference)
#include <cuda_runtime.h>
#include <cuda_fp16.h>
#include <math.h>

#define T_LEN 2048
#define DIM   768
#define NH    12
#define HD    64

// ---------------- scratch (no allocation allowed) ----------------
__device__ __half g_xh[T_LEN * DIM];
__device__ __half g_wqh[DIM * DIM];
__device__ __half g_wkh[DIM * DIM];
__device__ __half g_wvh[DIM * DIM];
__device__ __half g_wph[DIM * DIM];
__device__ __half g_qh[T_LEN * DIM];
__device__ __half g_kh[T_LEN * DIM];
__device__ __half g_vth[DIM * T_LEN];   // V transposed: [dim][token]
__device__ __half g_yh[T_LEN * DIM];

// ---------------- helpers ----------------
__device__ __forceinline__ void mma16(float* c, const unsigned* a, const unsigned* b) {
    asm volatile(
        "mma.sync.aligned.m16n8k16.row.col.f32.f16.f16.f32 "
        "{%0,%1,%2,%3}, {%4,%5,%6,%7}, {%8,%9}, {%0,%1,%2,%3};\n"
        : "+f"(c[0]), "+f"(c[1]), "+f"(c[2]), "+f"(c[3])
        : "r"(a[0]), "r"(a[1]), "r"(a[2]), "r"(a[3]), "r"(b[0]), "r"(b[1]));
}

__device__ __forceinline__ void cp16(void* smem_dst, const void* gsrc) {
    unsigned d = (unsigned)__cvta_generic_to_shared(smem_dst);
    asm volatile("cp.async.ca.shared.global [%0], [%1], 16;\n" :: "r"(d), "l"(gsrc));
}

// ---------------- fp32 -> fp16 conversion pass ----------------
__global__ __launch_bounds__(256)
void cvt_half_kernel(const float* __restrict__ x,
                     const float* __restrict__ wq, const float* __restrict__ wk,
                     const float* __restrict__ wv, const float* __restrict__ wp,
                     __half* __restrict__ xh,
                     __half* __restrict__ wqh, __half* __restrict__ wkh,
                     __half* __restrict__ wvh, __half* __restrict__ wph)
{
    const int z = blockIdx.y;
    const float* s; __half* d; int n;
    switch (z) {
        case 0: s = x;  d = xh;  n = T_LEN * DIM; break;
        case 1: s = wq; d = wqh; n = DIM * DIM;   break;
        case 2: s = wk; d = wkh; n = DIM * DIM;   break;
        case 3: s = wv; d = wvh; n = DIM * DIM;   break;
        default: s = wp; d = wph; n = DIM * DIM;  break;
    }
    const int i = (blockIdx.x * 256 + threadIdx.x) * 4;
    if (i < n) {
        float4 v = *(const float4*)(s + i);
        *(__half2*)(d + i)     = __floats2half2_rn(v.x, v.y);
        *(__half2*)(d + i + 2) = __floats2half2_rn(v.z, v.w);
    }
}

// =====================================================================
// fp16 tensor-core GEMM:  C = A @ B^T   (A [M,K], B [N,K])
// CTA tile 128xBN, 8 warps. BN=128: warps 2x4 (warp 64x32).
//                            BN=64:  warps 4x2 (warp 32x32).
// KC=32 halves, 2-stage cp.async, prefetch-then-wait(1).
// mode 0: plain fp32 store.  mode 1 (BN=128 only): z<2 RMSNorm+RoPE half C;
//                            z==2 blend with vi -> TRANSPOSED half C (vT).
// =====================================================================
#define KC    32
#define HSTR  40          // halves per smem row (20 words; 20 % 8 == 4)
#define HSTRW 20

template <int BN>
__global__ __launch_bounds__(256, 2)
void gemm_f16(const __half* __restrict__ A,
              const __half* __restrict__ W0, const __half* __restrict__ W1,
              const __half* __restrict__ W2,
              void* C0v, void* C1v, void* C2v,
              const float* __restrict__ vi, const float* __restrict__ lamb_ptr,
              int mode, int M, int N, int K)
{
    constexpr int MWARPS = (BN == 128) ? 2 : 4;
    constexpr int NWARPS = 8 / MWARPS;
    constexpr int MI     = 128 / (MWARPS * 16);   // 4 or 2
    constexpr int WMROW  = 128 / MWARPS;          // 64 or 32
    constexpr int ROWS   = 128 + BN;
    constexpr int STGH   = ROWS * HSTR;           // halves per stage

    extern __shared__ char smraw[];
    __half* smh = (__half*)smraw;

    const int z = blockIdx.z;
    const __half* B = (z == 0) ? W0 : (z == 1) ? W1 : W2;
    void* Cv = (z == 0) ? C0v : (z == 1) ? C1v : C2v;

    const int tid  = threadIdx.x;
    const int lane = tid & 31;
    const int warp = tid >> 5;
    const int wm   = warp / NWARPS;
    const int wn   = warp % NWARPS;
    const int bm   = blockIdx.y * 128;
    const int bn   = blockIdx.x * BN;
    const int gr   = lane >> 2;
    const int tig  = lane & 3;

    // loader: one thread per tile row (64B = 4 cp16); A rows tid<128, B rows after
    const bool ld_act = (tid < ROWS);
    const int lmat = tid >> 7;
    const int lrow = lmat ? (tid - 128) : tid;
    const __half* lsrc = lmat ? B + (size_t)(bn + (lrow < BN ? lrow : 0)) * K
                              : A + (size_t)(bm + lrow) * K;

    float acc[MI][4][4];
#pragma unroll
    for (int mi = 0; mi < MI; mi++)
#pragma unroll
        for (int ni = 0; ni < 4; ni++)
#pragma unroll
            for (int r = 0; r < 4; r++) acc[mi][ni][r] = 0.f;

    const int nt = K / KC;   // 24

#define GLOAD2(T, STG) do {                                                    \
        if (ld_act) {                                                          \
            __half* dst_ = smh + (STG) * STGH + lmat * 128 * HSTR + lrow * HSTR; \
            const __half* s_ = lsrc + (T) * KC;                                \
            cp16(dst_, s_); cp16(dst_ + 8, s_ + 8);                            \
            cp16(dst_ + 16, s_ + 16); cp16(dst_ + 24, s_ + 24);                \
        }                                                                      \
    } while (0)

    GLOAD2(0, 0);
    asm volatile("cp.async.commit_group;\n");

    for (int t = 0; t < nt; t++) {
        if (t + 1 < nt) {
            GLOAD2(t + 1, (t + 1) & 1);
            asm volatile("cp.async.commit_group;\n");
            asm volatile("cp.async.wait_group 1;\n");
        } else {
            asm volatile("cp.async.wait_group 0;\n");
        }
        __syncthreads();

        const unsigned* As = (const unsigned*)(smh + (t & 1) * STGH);
        const unsigned* Bs = As + 128 * HSTRW;

#pragma unroll
        for (int ks2 = 0; ks2 < 2; ks2++) {
            unsigned a[MI][4], b[4][2];
#pragma unroll
            for (int mi = 0; mi < MI; mi++) {
                const int r = wm * WMROW + mi * 16 + gr;
                a[mi][0] = As[r * HSTRW + ks2 * 8 + tig];
                a[mi][1] = As[(r + 8) * HSTRW + ks2 * 8 + tig];
                a[mi][2] = As[r * HSTRW + ks2 * 8 + 4 + tig];
                a[mi][3] = As[(r + 8) * HSTRW + ks2 * 8 + 4 + tig];
            }
#pragma unroll
            for (int ni = 0; ni < 4; ni++) {
                const int n = wn * 32 + ni * 8 + gr;
                b[ni][0] = Bs[n * HSTRW + ks2 * 8 + tig];
                b[ni][1] = Bs[n * HSTRW + ks2 * 8 + 4 + tig];
            }
#pragma unroll
            for (int mi = 0; mi < MI; mi++)
#pragma unroll
                for (int ni = 0; ni < 4; ni++)
                    mma16(acc[mi][ni], a[mi], b[ni]);
        }
        __syncthreads();
    }

    if constexpr (BN == 128) {
        if (mode == 1 && z < 2) {
            // ---- RMSNorm + RoPE epilogue; half output ----
            float* st = (float*)smraw;            // [128][132]
#pragma unroll
            for (int mi = 0; mi < MI; mi++)
#pragma unroll
                for (int ni = 0; ni < 4; ni++) {
                    const int r0 = wm * WMROW + mi * 16 + gr;
                    const int c0 = wn * 32 + ni * 8 + tig * 2;
                    *(float2*)&st[r0 * 132 + c0]       = make_float2(acc[mi][ni][0], acc[mi][ni][1]);
                    *(float2*)&st[(r0 + 8) * 132 + c0] = make_float2(acc[mi][ni][2], acc[mi][ni][3]);
                }
            __syncthreads();

            const int r  = tid >> 1;
            const int hh = tid & 1;
            const float* row = st + r * 132 + hh * 64;

            float x1[32], x2[32];
            float ss = 0.f;
#pragma unroll
            for (int i4 = 0; i4 < 8; i4++) {
                float4 u = *(const float4*)&row[i4 * 4];
                float4 w = *(const float4*)&row[i4 * 4 + 32];
                x1[i4*4+0] = u.x; x1[i4*4+1] = u.y; x1[i4*4+2] = u.z; x1[i4*4+3] = u.w;
                x2[i4*4+0] = w.x; x2[i4*4+1] = w.y; x2[i4*4+2] = w.z; x2[i4*4+3] = w.w;
                ss += u.x*u.x + u.y*u.y + u.z*u.z + u.w*u.w;
                ss += w.x*w.x + w.y*w.y + w.z*w.z + w.w*w.w;
            }
            const float rn = rsqrtf(ss * (1.f / 64.f) + 1.1920929e-07f);

            const int tok = bm + r;
            __half* Crow = (__half*)Cv + (size_t)tok * N + bn + hh * 64;
#pragma unroll
            for (int j2 = 0; j2 < 16; j2++) {
                float o1a, o1b, o2a, o2b;
#pragma unroll
                for (int e = 0; e < 2; e++) {
                    const int j = j2 * 2 + e;
                    const float inv = expf(-(float)j * 0.28782313662425572f); // ln(1e4)/32
                    const float ang = (float)tok * inv;
                    const float c = cosf(ang);
                    const float s = sinf(ang);
                    const float a1 = x1[j] * rn, a2 = x2[j] * rn;
                    const float o1 =  a1 * c + a2 * s;
                    const float o2 = -a1 * s + a2 * c;
                    if (e == 0) { o1a = o1; o2a = o2; } else { o1b = o1; o2b = o2; }
                }
                *(__half2*)&Crow[j2 * 2]      = __floats2half2_rn(o1a, o1b);
                *(__half2*)&Crow[32 + j2 * 2] = __floats2half2_rn(o2a, o2b);
            }
            return;
        }

        if (mode == 1) {
            // ---- V: blend with vi, store TRANSPOSED half ([dim][token]) ----
            __half* sh = (__half*)smraw;          // [128][136]
            const float lb = *lamb_ptr;
            const float om = 1.f - lb;
#pragma unroll
            for (int mi = 0; mi < MI; mi++)
#pragma unroll
                for (int ni = 0; ni < 4; ni++) {
                    const int r0 = wm * WMROW + mi * 16 + gr;
                    const int c0 = wn * 32 + ni * 8 + tig * 2;
                    const float* s0 = vi + (size_t)(bm + r0) * N + bn + c0;
                    const float* s1 = vi + (size_t)(bm + r0 + 8) * N + bn + c0;
                    *(__half2*)&sh[r0 * 136 + c0] = __floats2half2_rn(
                        om * acc[mi][ni][0] + lb * s0[0], om * acc[mi][ni][1] + lb * s0[1]);
                    *(__half2*)&sh[(r0 + 8) * 136 + c0] = __floats2half2_rn(
                        om * acc[mi][ni][2] + lb * s1[0], om * acc[mi][ni][3] + lb * s1[1]);
                }
            __syncthreads();

            const int cl = tid >> 1;      // dim within tile 0..127
            const int th = tid & 1;       // token half
            __half* dst = (__half*)Cv + (size_t)(bn + cl) * T_LEN + bm + th * 64;
#pragma unroll
            for (int j = 0; j < 32; j++) {
                __half a0 = sh[(th * 64 + 2 * j) * 136 + cl];
                __half a1 = sh[(th * 64 + 2 * j + 1) * 136 + cl];
                *(__half2*)&dst[2 * j] = __halves2half2(a0, a1);
            }
            return;
        }
    }

    // ---- mode 0: plain fp32 store ----
    float* C = (float*)Cv;
#pragma unroll
    for (int mi = 0; mi < MI; mi++) {
#pragma unroll
        for (int ni = 0; ni < 4; ni++) {
            const int r0 = bm + wm * WMROW + mi * 16 + gr;
            const int c0 = bn + wn * 32 + ni * 8 + tig * 2;
            *(float2*)(C + (size_t)r0 * N + c0)       = make_float2(acc[mi][ni][0], acc[mi][ni][1]);
            *(float2*)(C + (size_t)(r0 + 8) * N + c0) = make_float2(acc[mi][ni][2], acc[mi][ni][3]);
        }
    }
}

#define GEMM_SMEM_128 69632     // >= max(2*256*40*2, 128*132*4)
#define GEMM_SMEM_64  30720     // 2 stages * 192 rows * 40 halves * 2B

// =====================================================================
// fp16 tensor-core causal flash attention (fixed-shift softmax)
// CTA = (128-query block, head); 8 warps; 2 CTAs/SM.
// Inner loop over 64-key blocks, double-buffered K/V.
// =====================================================================
#define ATQ   128
#define ASTRH 72     // halves per row (36 words; 36 % 8 == 4: conflict-free)
#define ASTRW 36
#define AK_OFF 0
#define AV_OFF (2 * 64 * ASTRH)
#define AP_OFF (AV_OFF + 2 * 64 * ASTRH)
#define ATTN_SMEM_BYTES ((AP_OFF + ATQ * ASTRH) * 2)   // 55296

__global__ __launch_bounds__(256, 2)
void attn_f16(const __half* __restrict__ q, const __half* __restrict__ k,
              const __half* __restrict__ vt, __half* __restrict__ y)
{
    extern __shared__ char smraw[];
    __half* smh = (__half*)smraw;
    __half* k_s = smh + AK_OFF;   // [2][64][72]
    __half* v_s = smh + AV_OFF;   // [2][64][72]
    __half* p_s = smh + AP_OFF;   // [128][72]

    const int h   = blockIdx.x;
    const int qt  = (gridDim.y - 1) - blockIdx.y;     // longest-first
    const int q0  = qt * ATQ;
    const int tid = threadIdx.x;
    const int w    = tid >> 5;        // 0..7
    const int lane = tid & 31;
    const int gr   = lane >> 2;
    const int tig  = lane & 3;
    const int wrow = w * 16;          // 0..112

    // Q fragments (raw fp16 bits; scale applied post-MMA)
    unsigned aq[4][4];
    {
        const __half* qb_ = q + (size_t)(q0 + wrow) * DIM + h * HD;
#pragma unroll
        for (int ks2 = 0; ks2 < 4; ks2++) {
            aq[ks2][0] = *(const unsigned*)&qb_[(size_t)gr * DIM + ks2 * 16 + 2 * tig];
            aq[ks2][1] = *(const unsigned*)&qb_[(size_t)(gr + 8) * DIM + ks2 * 16 + 2 * tig];
            aq[ks2][2] = *(const unsigned*)&qb_[(size_t)gr * DIM + ks2 * 16 + 8 + 2 * tig];
            aq[ks2][3] = *(const unsigned*)&qb_[(size_t)(gr + 8) * DIM + ks2 * 16 + 8 + 2 * tig];
        }
    }

    float oacc[8][4];
#pragma unroll
    for (int ni = 0; ni < 8; ni++)
#pragma unroll
        for (int r = 0; r < 4; r++) oacc[ni][r] = 0.f;
    float l0 = 0.f, l1 = 0.f;

    // loader: warps 0-3 load K (64 rows x 128B), warps 4-7 load V^T (64 rows x 128B)
    const int lr = (tid & 127) >> 1;      // 0..63
    const int lc = (tid & 1) * 32;        // halves
    const bool isV = tid >= 128;
#define LOAD_KV(KB, STG) do {                                                  \
        const __half* g_ = isV ? vt + (size_t)(h * HD + lr) * T_LEN + (KB) * 64 + lc \
                               : k + (size_t)((KB) * 64 + lr) * DIM + h * HD + lc;   \
        __half* d_ = (isV ? v_s : k_s) + (STG) * 64 * ASTRH + lr * ASTRH + lc; \
        cp16(d_, g_); cp16(d_ + 8, g_ + 8);                                    \
        cp16(d_ + 16, g_ + 16); cp16(d_ + 24, g_ + 24);                        \
    } while (0)

    const int nkb = 2 * qt + 2;           // number of 64-key blocks

    LOAD_KV(0, 0);
    asm volatile("cp.async.commit_group;\n");

    for (int kb = 0; kb < nkb; kb++) {
        if (kb + 1 < nkb) {
            LOAD_KV(kb + 1, (kb + 1) & 1);
            asm volatile("cp.async.commit_group;\n");
            asm volatile("cp.async.wait_group 1;\n");
        } else {
            asm volatile("cp.async.wait_group 0;\n");
        }
        __syncthreads();

        const unsigned* Kw = (const unsigned*)(k_s + (kb & 1) * 64 * ASTRH);
        const unsigned* Vw = (const unsigned*)(v_s + (kb & 1) * 64 * ASTRH);

        // ---- S = Q K^T (raw) ----
        float sc[8][4];
#pragma unroll
        for (int ni = 0; ni < 8; ni++)
#pragma unroll
            for (int r = 0; r < 4; r++) sc[ni][r] = 0.f;

#pragma unroll
        for (int ni = 0; ni < 8; ni++) {
            const unsigned* kr = Kw + (ni * 8 + gr) * ASTRW + tig;
#pragma unroll
            for (int ks2 = 0; ks2 < 4; ks2++) {
                unsigned b[2];
                b[0] = kr[ks2 * 8];
                b[1] = kr[ks2 * 8 + 4];
                mma16(sc[ni], aq[ks2], b);
            }
        }

        // ---- fixed-shift softmax (scale 0.125 post-MMA), P as fp16 ----
        const int koff = kb * 64 - q0;        // key offset relative to query rows
        const bool diag = (koff > -64);       // only the last two blocks can mask
        const int r0 = wrow + gr, r1 = r0 + 8;
#pragma unroll
        for (int ni = 0; ni < 8; ni++) {
            const int c0 = ni * 8 + 2 * tig;
            float p0 = __expf(fmaf(sc[ni][0], 0.125f, -8.f));
            float p1 = __expf(fmaf(sc[ni][1], 0.125f, -8.f));
            float p2 = __expf(fmaf(sc[ni][2], 0.125f, -8.f));
            float p3 = __expf(fmaf(sc[ni][3], 0.125f, -8.f));
            if (diag) {
                if (c0 + koff > r0)     p0 = 0.f;
                if (c0 + 1 + koff > r0) p1 = 0.f;
                if (c0 + koff > r1)     p2 = 0.f;
                if (c0 + 1 + koff > r1) p3 = 0.f;
            }
            l0 += p0 + p1;
            l1 += p2 + p3;
            *(__half2*)&p_s[r0 * ASTRH + c0] = __floats2half2_rn(p0, p1);
            *(__half2*)&p_s[r1 * ASTRH + c0] = __floats2half2_rn(p2, p3);
        }
        __syncwarp();

        // ---- O += P V  (B = V^T tile: [dim][key]) ----
        const unsigned* Pw = (const unsigned*)p_s;
#pragma unroll
        for (int ks2 = 0; ks2 < 4; ks2++) {
            unsigned ap[4];
            ap[0] = Pw[r0 * ASTRW + ks2 * 8 + tig];
            ap[1] = Pw[r1 * ASTRW + ks2 * 8 + tig];
            ap[2] = Pw[r0 * ASTRW + ks2 * 8 + 4 + tig];
            ap[3] = Pw[r1 * ASTRW + ks2 * 8 + 4 + tig];
#pragma unroll
            for (int ni = 0; ni < 8; ni++) {
                const unsigned* vr = Vw + (ni * 8 + gr) * ASTRW + tig;
                unsigned b[2];
                b[0] = vr[ks2 * 8];
                b[1] = vr[ks2 * 8 + 4];
                mma16(oacc[ni], ap, b);
            }
        }
        __syncthreads();   // protect stage being overwritten by next prefetch
    }

    l0 += __shfl_xor_sync(0xffffffffu, l0, 1);
    l0 += __shfl_xor_sync(0xffffffffu, l0, 2);
    l1 += __shfl_xor_sync(0xffffffffu, l1, 1);
    l1 += __shfl_xor_sync(0xffffffffu, l1, 2);
    const float inv0 = 1.f / l0;
    const float inv1 = 1.f / l1;

    const int r0 = wrow + gr;
#pragma unroll
    for (int ni = 0; ni < 8; ni++) {
        const int c = ni * 8 + 2 * tig;
        *(__half2*)&y[(size_t)(q0 + r0) * DIM + h * HD + c] =
            __floats2half2_rn(oacc[ni][0] * inv0, oacc[ni][1] * inv0);
        *(__half2*)&y[(size_t)(q0 + r0 + 8) * DIM + h * HD + c] =
            __floats2half2_rn(oacc[ni][2] * inv1, oacc[ni][3] * inv1);
    }
}

// ---------------- launch ----------------
extern "C" void kernel_launch(void* const* d_in, const int* in_sizes, int n_in,
                              void* d_out, int out_size)
{
    const float* x    = (const float*)d_in[0];
    const float* vi   = (const float*)d_in[1];
    const float* Wq   = (const float*)d_in[2];
    const float* Wk   = (const float*)d_in[3];
    const float* Wv   = (const float*)d_in[4];
    const float* Wp   = (const float*)d_in[5];
    const float* lamb = (const float*)d_in[6];
    float* out = (float*)d_out;

    __half *xh, *wqh, *wkh, *wvh, *wph, *qh, *kh, *vth, *yh;
    cudaGetSymbolAddress((void**)&xh,  g_xh);
    cudaGetSymbolAddress((void**)&wqh, g_wqh);
    cudaGetSymbolAddress((void**)&wkh, g_wkh);
    cudaGetSymbolAddress((void**)&wvh, g_wvh);
    cudaGetSymbolAddress((void**)&wph, g_wph);
    cudaGetSymbolAddress((void**)&qh,  g_qh);
    cudaGetSymbolAddress((void**)&kh,  g_kh);
    cudaGetSymbolAddress((void**)&vth, g_vth);
    cudaGetSymbolAddress((void**)&yh,  g_yh);

    cudaFuncSetAttribute(gemm_f16<128>, cudaFuncAttributeMaxDynamicSharedMemorySize,
                         GEMM_SMEM_128);
    cudaFuncSetAttribute(gemm_f16<64>, cudaFuncAttributeMaxDynamicSharedMemorySize,
                         GEMM_SMEM_64);
    cudaFuncSetAttribute(attn_f16, cudaFuncAttributeMaxDynamicSharedMemorySize,
                         ATTN_SMEM_BYTES);

    // fp32 -> fp16 conversion of x and all weights
    dim3 gcvt((T_LEN * DIM / 4 + 255) / 256, 5);
    cvt_half_kernel<<<gcvt, 256>>>(x, Wq, Wk, Wv, Wp, xh, wqh, wkh, wvh, wph);

    // fused QKV: z=0/1 -> q/k (norm+rope, half), z=2 -> blended V transposed
    dim3 gqkv(DIM / 128, T_LEN / 128, 3);
    gemm_f16<128><<<gqkv, 256, GEMM_SMEM_128>>>(xh, wqh, wkh, wvh, qh, kh, vth,
                                                vi, lamb, 1, T_LEN, DIM, DIM);

    // fp16 tensor-core causal attention (128-query CTAs, 8 warps)
    dim3 gattn(NH, T_LEN / ATQ);
    attn_f16<<<gattn, 256, ATTN_SMEM_BYTES>>>(qh, kh, vth, yh);

    // output projection (fp32 out), 128x64 tiles -> 192 CTAs
    dim3 gproj(DIM / 64, T_LEN / 128, 1);
    gemm_f16<64><<<gproj, 256, GEMM_SMEM_64>>>(yh, wph, wph, wph, out, out, out,
                                               nullptr, nullptr, 0, T_LEN, DIM, DIM);
}

// round 12
// speedup vs baseline: 1.2299x; 1.2299x over previous
#include <cuda_runtime.h>
#include <cuda_fp16.h>
#include <math.h>

#define T_LEN 2048
#define DIM   768
#define NH    12
#define HD    64

// ---------------- scratch (no allocation allowed) ----------------
__device__ __half g_xh[T_LEN * DIM];
__device__ __half g_wqh[DIM * DIM];
__device__ __half g_wkh[DIM * DIM];
__device__ __half g_wvh[DIM * DIM];
__device__ __half g_wph[DIM * DIM];
__device__ __half g_qh[T_LEN * DIM];
__device__ __half g_kh[T_LEN * DIM];
__device__ __half g_vth[DIM * T_LEN];   // V transposed: [dim][token]
__device__ __half g_yh[T_LEN * DIM];

// ---------------- helpers ----------------
__device__ __forceinline__ void mma16(float* c, const unsigned* a, const unsigned* b) {
    asm volatile(
        "mma.sync.aligned.m16n8k16.row.col.f32.f16.f16.f32 "
        "{%0,%1,%2,%3}, {%4,%5,%6,%7}, {%8,%9}, {%0,%1,%2,%3};\n"
        : "+f"(c[0]), "+f"(c[1]), "+f"(c[2]), "+f"(c[3])
        : "r"(a[0]), "r"(a[1]), "r"(a[2]), "r"(a[3]), "r"(b[0]), "r"(b[1]));
}

__device__ __forceinline__ void cp16(void* smem_dst, const void* gsrc) {
    unsigned d = (unsigned)__cvta_generic_to_shared(smem_dst);
    asm volatile("cp.async.ca.shared.global [%0], [%1], 16;\n" :: "r"(d), "l"(gsrc));
}

__device__ __forceinline__ void ldm4(unsigned* r, unsigned saddr) {
    asm volatile("ldmatrix.sync.aligned.m8n8.x4.shared.b16 {%0,%1,%2,%3}, [%4];"
                 : "=r"(r[0]), "=r"(r[1]), "=r"(r[2]), "=r"(r[3]) : "r"(saddr));
}

// ---------------- fp32 -> fp16 conversion pass ----------------
__global__ __launch_bounds__(256)
void cvt_half_kernel(const float* __restrict__ x,
                     const float* __restrict__ wq, const float* __restrict__ wk,
                     const float* __restrict__ wv, const float* __restrict__ wp,
                     __half* __restrict__ xh,
                     __half* __restrict__ wqh, __half* __restrict__ wkh,
                     __half* __restrict__ wvh, __half* __restrict__ wph)
{
    const int z = blockIdx.y;
    const float* s; __half* d; int n;
    switch (z) {
        case 0: s = x;  d = xh;  n = T_LEN * DIM; break;
        case 1: s = wq; d = wqh; n = DIM * DIM;   break;
        case 2: s = wk; d = wkh; n = DIM * DIM;   break;
        case 3: s = wv; d = wvh; n = DIM * DIM;   break;
        default: s = wp; d = wph; n = DIM * DIM;  break;
    }
    const int i = (blockIdx.x * 256 + threadIdx.x) * 4;
    if (i < n) {
        float4 v = *(const float4*)(s + i);
        *(__half2*)(d + i)     = __floats2half2_rn(v.x, v.y);
        *(__half2*)(d + i + 2) = __floats2half2_rn(v.z, v.w);
    }
}

// =====================================================================
// fp16 tensor-core GEMM:  C = A @ B^T   (A [M,K], B [N,K])
// CTA 128x128, 8 warps (2x4), warp tile 64x32. KC=32 halves, 2-stage
// cp.async. Fragment loads via ldmatrix.x4.
// mode 0: plain fp32 store.  mode 1: z<2 RMSNorm+RoPE -> half C;
//                            z==2 blend with vi -> TRANSPOSED half C (vT).
// =====================================================================
#define KC    32
#define HSTR  40          // halves per smem row (20 words; 20 % 8 == 4)
#define STG_HALVES (2 * 128 * HSTR)
#define STG_BYTES  (STG_HALVES * 2)
#define GEMM_SMEM_BYTES 69632      // >= max(2*STG_HALVES*2, 128*132*4)

__global__ __launch_bounds__(256, 2)
void gemm_f16(const __half* __restrict__ A,
              const __half* __restrict__ W0, const __half* __restrict__ W1,
              const __half* __restrict__ W2,
              void* C0v, void* C1v, void* C2v,
              const float* __restrict__ vi, const float* __restrict__ lamb_ptr,
              int mode, int M, int N, int K)
{
    extern __shared__ char smraw[];
    __half* smh = (__half*)smraw;
    const unsigned sbase = (unsigned)__cvta_generic_to_shared(smraw);

    const int z = blockIdx.z;
    const __half* B = (z == 0) ? W0 : (z == 1) ? W1 : W2;
    void* Cv = (z == 0) ? C0v : (z == 1) ? C1v : C2v;

    const int tid  = threadIdx.x;
    const int lane = tid & 31;
    const int warp = tid >> 5;
    const int wm   = warp >> 2;
    const int wn   = warp & 3;
    const int bm   = blockIdx.y * 128;
    const int bn   = blockIdx.x * 128;
    const int gr   = lane >> 2;
    const int tig  = lane & 3;

    const int lmat = tid >> 7;
    const int lrow = tid & 127;
    const __half* lsrc = lmat ? B + (size_t)(bn + lrow) * K
                              : A + (size_t)(bm + lrow) * K;

    // ldmatrix per-lane byte offsets (relative to stage base)
    unsigned aoff[4], boff[2];
#pragma unroll
    for (int mi = 0; mi < 4; mi++)
        aoff[mi] = (unsigned)(((wm * 64 + mi * 16 + (lane & 15)) * HSTR
                               + (lane >> 4) * 8) * 2);
#pragma unroll
    for (int pr = 0; pr < 2; pr++)
        boff[pr] = (unsigned)((128 * HSTR
                               + (wn * 32 + pr * 16 + (lane >> 4) * 8 + (lane & 7)) * HSTR
                               + ((lane >> 3) & 1) * 8) * 2);

    float acc[4][4][4];
#pragma unroll
    for (int mi = 0; mi < 4; mi++)
#pragma unroll
        for (int ni = 0; ni < 4; ni++)
#pragma unroll
            for (int r = 0; r < 4; r++) acc[mi][ni][r] = 0.f;

    const int nt = K / KC;

#define GLOAD(T, STG) do {                                                   \
        __half* dst_ = smh + (STG) * STG_HALVES + lmat * 128 * HSTR + lrow * HSTR; \
        const __half* s_ = lsrc + (T) * KC;                                  \
        cp16(dst_, s_); cp16(dst_ + 8, s_ + 8);                              \
        cp16(dst_ + 16, s_ + 16); cp16(dst_ + 24, s_ + 24);                  \
    } while (0)

    GLOAD(0, 0);
    asm volatile("cp.async.commit_group;\n");

    for (int t = 0; t < nt; t++) {
        if (t + 1 < nt) {
            GLOAD(t + 1, (t + 1) & 1);
            asm volatile("cp.async.commit_group;\n");
            asm volatile("cp.async.wait_group 1;\n");
        } else {
            asm volatile("cp.async.wait_group 0;\n");
        }
        __syncthreads();

        const unsigned stg = sbase + (t & 1) * STG_BYTES;

#pragma unroll
        for (int ks2 = 0; ks2 < 2; ks2++) {
            unsigned a[4][4], b[4][2];
#pragma unroll
            for (int mi = 0; mi < 4; mi++)
                ldm4(a[mi], stg + aoff[mi] + ks2 * 32);
#pragma unroll
            for (int pr = 0; pr < 2; pr++) {
                unsigned r4[4];
                ldm4(r4, stg + boff[pr] + ks2 * 32);
                b[2*pr][0] = r4[0]; b[2*pr][1] = r4[1];
                b[2*pr+1][0] = r4[2]; b[2*pr+1][1] = r4[3];
            }
#pragma unroll
            for (int mi = 0; mi < 4; mi++)
#pragma unroll
                for (int ni = 0; ni < 4; ni++)
                    mma16(acc[mi][ni], a[mi], b[ni]);
        }
        __syncthreads();
    }

    if (mode == 1 && z < 2) {
        // ---- RMSNorm + RoPE epilogue; half output ----
        float* st = (float*)smraw;            // [128][132]
#pragma unroll
        for (int mi = 0; mi < 4; mi++)
#pragma unroll
            for (int ni = 0; ni < 4; ni++) {
                const int r0 = wm * 64 + mi * 16 + gr;
                const int c0 = wn * 32 + ni * 8 + tig * 2;
                *(float2*)&st[r0 * 132 + c0]       = make_float2(acc[mi][ni][0], acc[mi][ni][1]);
                *(float2*)&st[(r0 + 8) * 132 + c0] = make_float2(acc[mi][ni][2], acc[mi][ni][3]);
            }
        __syncthreads();

        const int r  = tid >> 1;
        const int hh = tid & 1;
        const float* row = st + r * 132 + hh * 64;

        float x1[32], x2[32];
        float ss = 0.f;
#pragma unroll
        for (int i4 = 0; i4 < 8; i4++) {
            float4 u = *(const float4*)&row[i4 * 4];
            float4 w = *(const float4*)&row[i4 * 4 + 32];
            x1[i4*4+0] = u.x; x1[i4*4+1] = u.y; x1[i4*4+2] = u.z; x1[i4*4+3] = u.w;
            x2[i4*4+0] = w.x; x2[i4*4+1] = w.y; x2[i4*4+2] = w.z; x2[i4*4+3] = w.w;
            ss += u.x*u.x + u.y*u.y + u.z*u.z + u.w*u.w;
            ss += w.x*w.x + w.y*w.y + w.z*w.z + w.w*w.w;
        }
        const float rn = rsqrtf(ss * (1.f / 64.f) + 1.1920929e-07f);

        const int tok = bm + r;
        __half* Crow = (__half*)Cv + (size_t)tok * N + bn + hh * 64;
#pragma unroll
        for (int j2 = 0; j2 < 16; j2++) {
            float o1a, o1b, o2a, o2b;
#pragma unroll
            for (int e = 0; e < 2; e++) {
                const int j = j2 * 2 + e;
                const float inv = expf(-(float)j * 0.28782313662425572f); // ln(1e4)/32
                const float ang = (float)tok * inv;
                const float c = cosf(ang);
                const float s = sinf(ang);
                const float a1 = x1[j] * rn, a2 = x2[j] * rn;
                const float o1 =  a1 * c + a2 * s;
                const float o2 = -a1 * s + a2 * c;
                if (e == 0) { o1a = o1; o2a = o2; } else { o1b = o1; o2b = o2; }
            }
            *(__half2*)&Crow[j2 * 2]      = __floats2half2_rn(o1a, o1b);
            *(__half2*)&Crow[32 + j2 * 2] = __floats2half2_rn(o2a, o2b);
        }
        return;
    }

    if (mode == 1) {
        // ---- V: blend with vi, store TRANSPOSED half ([dim][token]) ----
        __half* sh = (__half*)smraw;          // [128][136]
        const float lb = *lamb_ptr;
        const float om = 1.f - lb;
#pragma unroll
        for (int mi = 0; mi < 4; mi++)
#pragma unroll
            for (int ni = 0; ni < 4; ni++) {
                const int r0 = wm * 64 + mi * 16 + gr;
                const int c0 = wn * 32 + ni * 8 + tig * 2;
                const float* s0 = vi + (size_t)(bm + r0) * N + bn + c0;
                const float* s1 = vi + (size_t)(bm + r0 + 8) * N + bn + c0;
                *(__half2*)&sh[r0 * 136 + c0] = __floats2half2_rn(
                    om * acc[mi][ni][0] + lb * s0[0], om * acc[mi][ni][1] + lb * s0[1]);
                *(__half2*)&sh[(r0 + 8) * 136 + c0] = __floats2half2_rn(
                    om * acc[mi][ni][2] + lb * s1[0], om * acc[mi][ni][3] + lb * s1[1]);
            }
        __syncthreads();

        const int cl = tid >> 1;      // dim within tile 0..127
        const int th = tid & 1;       // token half
        __half* dst = (__half*)Cv + (size_t)(bn + cl) * T_LEN + bm + th * 64;
#pragma unroll
        for (int j = 0; j < 32; j++) {
            __half a0 = sh[(th * 64 + 2 * j) * 136 + cl];
            __half a1 = sh[(th * 64 + 2 * j + 1) * 136 + cl];
            *(__half2*)&dst[2 * j] = __halves2half2(a0, a1);
        }
        return;
    }

    // ---- mode 0: plain fp32 store ----
    float* C = (float*)Cv;
#pragma unroll
    for (int mi = 0; mi < 4; mi++) {
#pragma unroll
        for (int ni = 0; ni < 4; ni++) {
            const int r0 = bm + wm * 64 + mi * 16 + gr;
            const int c0 = bn + wn * 32 + ni * 8 + tig * 2;
            *(float2*)(C + (size_t)r0 * N + c0)       = make_float2(acc[mi][ni][0], acc[mi][ni][1]);
            *(float2*)(C + (size_t)(r0 + 8) * N + c0) = make_float2(acc[mi][ni][2], acc[mi][ni][3]);
        }
    }
}

// =====================================================================
// fp16 tensor-core causal flash attention (fixed-shift softmax)
// CTA = (64-query block, head); 4 warps; 4 CTAs/SM. ldmatrix fragments.
// =====================================================================
#define ASTRH 72     // halves per row (36 words; 36 % 8 == 4: conflict-free)
#define AT_K 0
#define AT_V (2 * 64 * ASTRH)
#define AT_P (AT_V + 2 * 64 * ASTRH)
#define ATTN_SMEM_BYTES ((AT_P + 64 * ASTRH) * 2)   // 46080

__global__ __launch_bounds__(128, 4)
void attn_f16(const __half* __restrict__ q, const __half* __restrict__ k,
              const __half* __restrict__ vt, __half* __restrict__ y)
{
    extern __shared__ char smraw[];
    __half* smh = (__half*)smraw;
    __half* k_s = smh + AT_K;
    __half* v_s = smh + AT_V;
    __half* p_s = smh + AT_P;
    const unsigned sbase = (unsigned)__cvta_generic_to_shared(smraw);

    const int h   = blockIdx.x;
    const int qb  = (gridDim.y - 1) - blockIdx.y;     // longest-first
    const int q0  = qb * 64;
    const int tid = threadIdx.x;
    const int w    = tid >> 5;
    const int lane = tid & 31;
    const int gr   = lane >> 2;
    const int tig  = lane & 3;
    const int wrow = w * 16;

    // Q fragments (raw fp16 bits; scale applied post-MMA)
    unsigned aq[4][4];
    {
        const __half* qb_ = q + (size_t)(q0 + wrow) * DIM + h * HD;
#pragma unroll
        for (int ks2 = 0; ks2 < 4; ks2++) {
            aq[ks2][0] = *(const unsigned*)&qb_[(size_t)gr * DIM + ks2 * 16 + 2 * tig];
            aq[ks2][1] = *(const unsigned*)&qb_[(size_t)(gr + 8) * DIM + ks2 * 16 + 2 * tig];
            aq[ks2][2] = *(const unsigned*)&qb_[(size_t)gr * DIM + ks2 * 16 + 8 + 2 * tig];
            aq[ks2][3] = *(const unsigned*)&qb_[(size_t)(gr + 8) * DIM + ks2 * 16 + 8 + 2 * tig];
        }
    }

    // ldmatrix per-lane byte offsets
    unsigned kvoff[4];   // K and V share stride; pair pr covers ni 2pr,2pr+1
#pragma unroll
    for (int pr = 0; pr < 4; pr++)
        kvoff[pr] = (unsigned)(((pr * 16 + (lane >> 4) * 8 + (lane & 7)) * ASTRH
                                + ((lane >> 3) & 1) * 8) * 2);
    const unsigned poff = (unsigned)(AT_P * 2
                          + ((wrow + (lane & 15)) * ASTRH + (lane >> 4) * 8) * 2);

    float oacc[8][4];
#pragma unroll
    for (int ni = 0; ni < 8; ni++)
#pragma unroll
        for (int r = 0; r < 4; r++) oacc[ni][r] = 0.f;
    float l0 = 0.f, l1 = 0.f;

    const int ar = tid >> 1;
    const int ac = (tid & 1) * 32;
#define LOAD_KV(KB, STG) do {                                                  \
        const __half* kg = k + (size_t)((KB) * 64 + ar) * DIM + h * HD + ac;   \
        const __half* vg = vt + (size_t)(h * HD + ar) * T_LEN + (KB) * 64 + ac;\
        __half* kd = k_s + (STG) * 64 * ASTRH + ar * ASTRH + ac;               \
        __half* vd = v_s + (STG) * 64 * ASTRH + ar * ASTRH + ac;               \
        cp16(kd, kg); cp16(kd + 8, kg + 8); cp16(kd + 16, kg + 16); cp16(kd + 24, kg + 24); \
        cp16(vd, vg); cp16(vd + 8, vg + 8); cp16(vd + 16, vg + 16); cp16(vd + 24, vg + 24); \
    } while (0)

    LOAD_KV(0, 0);
    asm volatile("cp.async.commit_group;\n");

    for (int kb = 0; kb <= qb; kb++) {
        if (kb < qb) {
            LOAD_KV(kb + 1, (kb + 1) & 1);
            asm volatile("cp.async.commit_group;\n");
            asm volatile("cp.async.wait_group 1;\n");
        } else {
            asm volatile("cp.async.wait_group 0;\n");
        }
        __syncthreads();

        const unsigned kstg = sbase + (AT_K + (kb & 1) * 64 * ASTRH) * 2;
        const unsigned vstg = sbase + (AT_V * 2) + (kb & 1) * 64 * ASTRH * 2;

        // ---- S = Q K^T (raw) ----
        float s[8][4];
#pragma unroll
        for (int ni = 0; ni < 8; ni++)
#pragma unroll
            for (int r = 0; r < 4; r++) s[ni][r] = 0.f;

#pragma unroll
        for (int ks2 = 0; ks2 < 4; ks2++) {
            unsigned b[8][2];
#pragma unroll
            for (int pr = 0; pr < 4; pr++) {
                unsigned r4[4];
                ldm4(r4, kstg + kvoff[pr] + ks2 * 32);
                b[2*pr][0] = r4[0]; b[2*pr][1] = r4[1];
                b[2*pr+1][0] = r4[2]; b[2*pr+1][1] = r4[3];
            }
#pragma unroll
            for (int ni = 0; ni < 8; ni++)
                mma16(s[ni], aq[ks2], b[ni]);
        }

        // ---- fixed-shift softmax (scale 0.125 post-MMA), P as fp16 ----
        const bool diag = (kb == qb);
        const int r0 = wrow + gr, r1 = r0 + 8;
#pragma unroll
        for (int ni = 0; ni < 8; ni++) {
            const int c0 = ni * 8 + 2 * tig;
            float p0 = __expf(fmaf(s[ni][0], 0.125f, -8.f));
            float p1 = __expf(fmaf(s[ni][1], 0.125f, -8.f));
            float p2 = __expf(fmaf(s[ni][2], 0.125f, -8.f));
            float p3 = __expf(fmaf(s[ni][3], 0.125f, -8.f));
            if (diag) {
                if (c0 > r0)     p0 = 0.f;
                if (c0 + 1 > r0) p1 = 0.f;
                if (c0 > r1)     p2 = 0.f;
                if (c0 + 1 > r1) p3 = 0.f;
            }
            l0 += p0 + p1;
            l1 += p2 + p3;
            *(__half2*)&p_s[r0 * ASTRH + c0] = __floats2half2_rn(p0, p1);
            *(__half2*)&p_s[r1 * ASTRH + c0] = __floats2half2_rn(p2, p3);
        }
        __syncwarp();

        // ---- O += P V  (B = V^T tile: [dim][key]) ----
#pragma unroll
        for (int ks2 = 0; ks2 < 4; ks2++) {
            unsigned ap[4];
            ldm4(ap, sbase + poff + ks2 * 32);
            unsigned b[8][2];
#pragma unroll
            for (int pr = 0; pr < 4; pr++) {
                unsigned r4[4];
                ldm4(r4, vstg + kvoff[pr] + ks2 * 32);
                b[2*pr][0] = r4[0]; b[2*pr][1] = r4[1];
                b[2*pr+1][0] = r4[2]; b[2*pr+1][1] = r4[3];
            }
#pragma unroll
            for (int ni = 0; ni < 8; ni++)
                mma16(oacc[ni], ap, b[ni]);
        }
        __syncthreads();
    }

    l0 += __shfl_xor_sync(0xffffffffu, l0, 1);
    l0 += __shfl_xor_sync(0xffffffffu, l0, 2);
    l1 += __shfl_xor_sync(0xffffffffu, l1, 1);
    l1 += __shfl_xor_sync(0xffffffffu, l1, 2);
    const float inv0 = 1.f / l0;
    const float inv1 = 1.f / l1;

    const int r0 = wrow + gr;
#pragma unroll
    for (int ni = 0; ni < 8; ni++) {
        const int c = ni * 8 + 2 * tig;
        *(__half2*)&y[(size_t)(q0 + r0) * DIM + h * HD + c] =
            __floats2half2_rn(oacc[ni][0] * inv0, oacc[ni][1] * inv0);
        *(__half2*)&y[(size_t)(q0 + r0 + 8) * DIM + h * HD + c] =
            __floats2half2_rn(oacc[ni][2] * inv1, oacc[ni][3] * inv1);
    }
}

// ---------------- launch ----------------
extern "C" void kernel_launch(void* const* d_in, const int* in_sizes, int n_in,
                              void* d_out, int out_size)
{
    const float* x    = (const float*)d_in[0];
    const float* vi   = (const float*)d_in[1];
    const float* Wq   = (const float*)d_in[2];
    const float* Wk   = (const float*)d_in[3];
    const float* Wv   = (const float*)d_in[4];
    const float* Wp   = (const float*)d_in[5];
    const float* lamb = (const float*)d_in[6];
    float* out = (float*)d_out;

    __half *xh, *wqh, *wkh, *wvh, *wph, *qh, *kh, *vth, *yh;
    cudaGetSymbolAddress((void**)&xh,  g_xh);
    cudaGetSymbolAddress((void**)&wqh, g_wqh);
    cudaGetSymbolAddress((void**)&wkh, g_wkh);
    cudaGetSymbolAddress((void**)&wvh, g_wvh);
    cudaGetSymbolAddress((void**)&wph, g_wph);
    cudaGetSymbolAddress((void**)&qh,  g_qh);
    cudaGetSymbolAddress((void**)&kh,  g_kh);
    cudaGetSymbolAddress((void**)&vth, g_vth);
    cudaGetSymbolAddress((void**)&yh,  g_yh);

    cudaFuncSetAttribute(gemm_f16, cudaFuncAttributeMaxDynamicSharedMemorySize,
                         GEMM_SMEM_BYTES);
    cudaFuncSetAttribute(attn_f16, cudaFuncAttributeMaxDynamicSharedMemorySize,
                         ATTN_SMEM_BYTES);

    // fp32 -> fp16 conversion of x and all weights
    dim3 gcvt((T_LEN * DIM / 4 + 255) / 256, 5);
    cvt_half_kernel<<<gcvt, 256>>>(x, Wq, Wk, Wv, Wp, xh, wqh, wkh, wvh, wph);

    // fused QKV: z=0/1 -> q/k (norm+rope, half), z=2 -> blended V transposed
    dim3 gqkv(DIM / 128, T_LEN / 128, 3);
    gemm_f16<<<gqkv, 256, GEMM_SMEM_BYTES>>>(xh, wqh, wkh, wvh, qh, kh, vth,
                                             vi, lamb, 1, T_LEN, DIM, DIM);

    // fp16 tensor-core causal attention
    dim3 gattn(NH, T_LEN / 64);
    attn_f16<<<gattn, 128, ATTN_SMEM_BYTES>>>(qh, kh, vth, yh);

    // output projection (fp32 out)
    dim3 gproj(DIM / 128, T_LEN / 128, 1);
    gemm_f16<<<gproj, 256, GEMM_SMEM_BYTES>>>(yh, wph, wph, wph, out, out, out,
                                              nullptr, nullptr, 0, T_LEN, DIM, DIM);
}